// round 14
// baseline (speedup 1.0000x reference)
#include <cuda_runtime.h>

#define NNODES 50000
#define NEDGES 800000
#define DIM 64
#define LAYERS 5
#define BN_EPS 1e-5f
#define SCAN_BLOCKS 196   // ceil(50000/256)

// Scratch (__device__ globals; allocation-free rule)
__device__ float g_H[NNODES * DIM];        // layer-0 input features only
__device__ float g_Z[NNODES * DIM];        // (1+eps)*h + agg  (GEMM1 input)
__device__ float g_P1[NNODES * 2 * DIM];   // hidden activations [N,128]
__device__ float g_P2[NNODES * DIM];       // mlp output pre-BN2 [N,64]
// stats: [0:128) s1 [128:256) q1 | s2/q2 parity slots: [256+p*128, +64) s2, +64..128 q2
__device__ float g_stats[512];
__device__ int   g_deg[NNODES];
__device__ int   g_off[NNODES];
__device__ int   g_cur[NNODES];
__device__ int   g_csr[NEDGES];
__device__ int   g_bsum[256];
__device__ int   g_src[NEDGES];            // src node per CSR position
__device__ float g_ea[NEDGES * 7];         // edge attrs permuted to CSR order

typedef unsigned long long u64;

// ---- packed f32x2 helpers ----
__device__ __forceinline__ u64 pkdup(float v) {
    u64 r; asm("mov.b64 %0, {%1, %1};" : "=l"(r) : "f"(v)); return r;
}
__device__ __forceinline__ void upk2(u64 v, float& lo, float& hi) {
    asm("mov.b64 {%0, %1}, %2;" : "=f"(lo), "=f"(hi) : "l"(v));
}
__device__ __forceinline__ void fma2(u64& d, u64 a, u64 b) {
    asm("fma.rn.f32x2 %0, %1, %2, %3;" : "=l"(d) : "l"(a), "l"(b), "l"(d));
}

// ---------------------------------------------------------------- init
__global__ void k_init(const int* __restrict__ x, const float* __restrict__ emb) {
    int i = blockIdx.x * blockDim.x + threadIdx.x;
    if (i < 512) g_stats[i] = 0.0f;
    if (i < NNODES) g_deg[i] = 0;
    if (i < NNODES * DIM) {
        int n = i >> 6, d = i & 63;
        g_H[i] = emb[x[n] * DIM + d];
    }
}

// ---------------------------------------------------- CSR build (per call)
__global__ void k_hist(const int* __restrict__ ei) {
    int e = blockIdx.x * blockDim.x + threadIdx.x;
    if (e < NEDGES) atomicAdd(&g_deg[__ldg(ei + NEDGES + e)], 1);
}

__global__ void k_scanA() {
    __shared__ int ws[8];
    int i = blockIdx.x * 256 + threadIdx.x;
    int lane = threadIdx.x & 31, w = threadIdx.x >> 5;
    int v = (i < NNODES) ? g_deg[i] : 0;
    int x = v;
#pragma unroll
    for (int o = 1; o < 32; o <<= 1) {
        int y = __shfl_up_sync(0xFFFFFFFFu, x, o);
        if (lane >= o) x += y;
    }
    if (lane == 31) ws[w] = x;
    __syncthreads();
    if (w == 0) {
        int y = (lane < 8) ? ws[lane] : 0;
#pragma unroll
        for (int o = 1; o < 8; o <<= 1) {
            int z = __shfl_up_sync(0xFFFFFFFFu, y, o);
            if (lane >= o) y += z;
        }
        if (lane < 8) ws[lane] = y;
    }
    __syncthreads();
    int base = (w > 0) ? ws[w - 1] : 0;
    int incl = x + base;
    if (i < NNODES) g_off[i] = incl - v;
    if (threadIdx.x == 255) g_bsum[blockIdx.x] = incl;
}

__global__ void k_scanB() {
    __shared__ int ws[8];
    int t = threadIdx.x;
    int lane = t & 31, w = t >> 5;
    int v = (t < SCAN_BLOCKS) ? g_bsum[t] : 0;
    int x = v;
#pragma unroll
    for (int o = 1; o < 32; o <<= 1) {
        int y = __shfl_up_sync(0xFFFFFFFFu, x, o);
        if (lane >= o) x += y;
    }
    if (lane == 31) ws[w] = x;
    __syncthreads();
    if (w == 0) {
        int y = (lane < 8) ? ws[lane] : 0;
#pragma unroll
        for (int o = 1; o < 8; o <<= 1) {
            int z = __shfl_up_sync(0xFFFFFFFFu, y, o);
            if (lane >= o) y += z;
        }
        if (lane < 8) ws[lane] = y;
    }
    __syncthreads();
    int base = (w > 0) ? ws[w - 1] : 0;
    if (t < SCAN_BLOCKS) g_bsum[t] = x + base - v;
}

__global__ void k_scanC() {
    int i = blockIdx.x * 256 + threadIdx.x;
    if (i < NNODES) {
        g_off[i] += g_bsum[blockIdx.x];
        g_cur[i] = 0;
    }
}

__global__ void k_scatter(const int* __restrict__ ei) {
    int e = blockIdx.x * blockDim.x + threadIdx.x;
    if (e < NEDGES) {
        int d = __ldg(ei + NEDGES + e);
        int p = atomicAdd(&g_cur[d], 1);
        g_csr[g_off[d] + p] = e;
    }
}

// Permute src ids and edge attrs into CSR order (one-time; sequential writes).
__global__ void k_permute(const int* __restrict__ ei, const float* __restrict__ ea) {
    int p = blockIdx.x * blockDim.x + threadIdx.x;
    if (p < NEDGES) {
        int e = g_csr[p];
        g_src[p] = __ldg(ei + e);
        const float* sp = ea + e * 7;
        float* dp = g_ea + p * 7;
#pragma unroll
        for (int k = 0; k < 7; k++) dp[k] = __ldg(sp + k);
    }
}

// -------- aggregation: one warp per node, no atomics (R6 loop), with BN2+ReLU
// of the PREVIOUS layer fused into the feature reads.
// Layer 0 (dobn=0): h = g_H raw.
// Layer l>=1 (dobn=1): h = relu(P2*sc2 + sh2) using stats parity slot rd_p.
// Block 0 zeroes stats [0:256) and parity slot wr_p for this layer.
__global__ void k_aggr(const float* __restrict__ We, const float* __restrict__ be,
                       const float* __restrict__ epsp,
                       const float* __restrict__ g2v, const float* __restrict__ bb2v,
                       int dobn, int rd_p, int wr_p) {
    if (blockIdx.x == 0) {
        g_stats[threadIdx.x] = 0.0f;                       // [0:256)
        if (threadIdx.x < 128) g_stats[256 + wr_p * 128 + threadIdx.x] = 0.0f;
    }
    int node = (blockIdx.x * blockDim.x + threadIdx.x) >> 5;
    if (node >= NNODES) return;
    int lane = threadIdx.x & 31;
    int j0 = 2 * lane, j1 = 2 * lane + 1;

    // BN2 transform of previous layer for this lane's two columns
    float sc0 = 1.0f, sh0 = 0.0f, sc1 = 1.0f, sh1 = 0.0f;
    const float* feat = g_H;
    if (dobn) {
        const float inv = 1.0f / (float)NNODES;
        int sb = 256 + rd_p * 128;
        float m0 = g_stats[sb + j0] * inv;
        float m1 = g_stats[sb + j1] * inv;
        float v0 = g_stats[sb + 64 + j0] * inv - m0 * m0;
        float v1 = g_stats[sb + 64 + j1] * inv - m1 * m1;
        float r0 = rsqrtf(v0 + BN_EPS) * __ldg(g2v + j0);
        float r1 = rsqrtf(v1 + BN_EPS) * __ldg(g2v + j1);
        sc0 = r0; sh0 = __ldg(bb2v + j0) - m0 * r0;
        sc1 = r1; sh1 = __ldg(bb2v + j1) - m1 * r1;
        feat = g_P2;
    }

    float2 w[7];
#pragma unroll
    for (int k = 0; k < 7; k++) w[k] = *(const float2*)(We + k * DIM + j0);
    float2 bv = *(const float2*)(be + j0);

    int beg = g_off[node];
    int end = (node == NNODES - 1) ? NEDGES : g_off[node + 1];

    float a0 = 0.0f, a1 = 0.0f;
#pragma unroll 2
    for (int p = beg; p < end; p++) {
        int s = __ldg(g_src + p);
        const float* ep = g_ea + p * 7;
        float m0 = bv.x, m1 = bv.y;
#pragma unroll
        for (int k = 0; k < 7; k++) {
            float a = __ldg(ep + k);
            m0 = fmaf(a, w[k].x, m0);
            m1 = fmaf(a, w[k].y, m1);
        }
        float2 h2 = *(const float2*)(feat + s * DIM + j0);
        float hx = h2.x, hy = h2.y;
        if (dobn) {
            hx = fmaxf(fmaf(hx, sc0, sh0), 0.0f);
            hy = fmaxf(fmaf(hy, sc1, sh1), 0.0f);
        }
        a0 += fmaxf(m0 + hx, 0.0f);
        a1 += fmaxf(m1 + hy, 0.0f);
    }

    float ev = 1.0f + __ldg(epsp);
    float2 hh = *(const float2*)(feat + node * DIM + j0);
    float hx = hh.x, hy = hh.y;
    if (dobn) {
        hx = fmaxf(fmaf(hx, sc0, sh0), 0.0f);
        hy = fmaxf(fmaf(hy, sc1, sh1), 0.0f);
    }
    *(float2*)(g_Z + node * DIM + j0) =
        make_float2(fmaf(ev, hx, a0), fmaf(ev, hy, a1));
}

// ---------------- GEMM1: P1 = Z @ W1 + b1, epilogue: colsum/colsq  (R6 form)
__global__ void k_gemm1(const float* __restrict__ W1, const float* __restrict__ b1) {
    __shared__ float zs[64 * 68];    // transposed [k][r]
    __shared__ float ws[64 * 128];
    int t = threadIdx.x;
    int row0 = blockIdx.x * 64;

    for (int i = t; i < 64 * 128; i += 256) ws[i] = W1[i];
    for (int i = t; i < 64 * 64; i += 256) {
        int r = i >> 6, k = i & 63;
        int gr = row0 + r;
        zs[k * 68 + r] = (gr < NNODES) ? g_Z[gr * 64 + k] : 0.0f;
    }
    __syncthreads();

    int tx = t & 31, ty = t >> 5;
    int j4 = tx * 4, r8 = ty * 8;
    u64 acc[4][4];
#pragma unroll
    for (int p = 0; p < 4; p++)
#pragma unroll
        for (int c = 0; c < 4; c++) acc[p][c] = 0ULL;

#pragma unroll 4
    for (int k = 0; k < 64; k++) {
        float4 wv = *(const float4*)(ws + k * 128 + j4);
        u64 wd[4] = {pkdup(wv.x), pkdup(wv.y), pkdup(wv.z), pkdup(wv.w)};
        ulonglong2 za = *(const ulonglong2*)(zs + k * 68 + r8);
        ulonglong2 zb = *(const ulonglong2*)(zs + k * 68 + r8 + 4);
        u64 zp[4] = {za.x, za.y, zb.x, zb.y};
#pragma unroll
        for (int p = 0; p < 4; p++) {
            fma2(acc[p][0], zp[p], wd[0]);
            fma2(acc[p][1], zp[p], wd[1]);
            fma2(acc[p][2], zp[p], wd[2]);
            fma2(acc[p][3], zp[p], wd[3]);
        }
    }

    float4 bv = *(const float4*)(b1 + j4);
    float cs[4] = {0, 0, 0, 0}, cq[4] = {0, 0, 0, 0};
#pragma unroll
    for (int p = 0; p < 4; p++) {
        float o[2][4];
#pragma unroll
        for (int c = 0; c < 4; c++) upk2(acc[p][c], o[0][c], o[1][c]);
#pragma unroll
        for (int h = 0; h < 2; h++) {
            int gr = row0 + r8 + 2 * p + h;
            float o0 = o[h][0] + bv.x, o1 = o[h][1] + bv.y;
            float o2 = o[h][2] + bv.z, o3 = o[h][3] + bv.w;
            if (gr < NNODES) {
                *(float4*)(g_P1 + gr * 128 + j4) = make_float4(o0, o1, o2, o3);
                cs[0] += o0; cq[0] += o0 * o0;
                cs[1] += o1; cq[1] += o1 * o1;
                cs[2] += o2; cq[2] += o2 * o2;
                cs[3] += o3; cq[3] += o3 * o3;
            }
        }
    }

    __syncthreads();
#pragma unroll
    for (int c = 0; c < 4; c++) {
        zs[ty * 128 + j4 + c] = cs[c];
        zs[1024 + ty * 128 + j4 + c] = cq[c];
    }
    __syncthreads();
    {
        int col = t & 127;
        int base = (t < 128) ? 0 : 1024;
        int off = (t < 128) ? 0 : 128;
        float v = 0.0f;
#pragma unroll
        for (int w = 0; w < 8; w++) v += zs[base + w * 128 + col];
        atomicAdd(g_stats + off + col, v);
    }
}

// -------- GEMM2: P2 = relu(BN1(P1)) @ W2 + b2; colsum/colsq -> parity slot wr_p
__global__ void k_gemm2(const float* __restrict__ W2, const float* __restrict__ b2,
                        const float* __restrict__ g1v, const float* __restrict__ bb1v,
                        int wr_p) {
    __shared__ float as[128 * 68];
    __shared__ float ws[128 * 64];
    __shared__ float sc[128], sh[128];
    int t = threadIdx.x;
    int row0 = blockIdx.x * 64;

    if (t < 128) {
        const float inv = 1.0f / (float)NNODES;
        float m = g_stats[t] * inv;
        float vq = g_stats[128 + t] * inv - m * m;
        float rs = rsqrtf(vq + BN_EPS);
        float s = rs * __ldg(g1v + t);
        sc[t] = s;
        sh[t] = __ldg(bb1v + t) - m * s;
    }
    for (int i = t; i < 128 * 64; i += 256) ws[i] = W2[i];
    __syncthreads();

    for (int i = t; i < 64 * 128; i += 256) {
        int r = i >> 7, k = i & 127;
        int gr = row0 + r;
        float v = 0.0f;
        if (gr < NNODES) v = fmaxf(g_P1[gr * 128 + k] * sc[k] + sh[k], 0.0f);
        as[k * 68 + r] = v;
    }
    __syncthreads();

    int tx = t & 31, ty = t >> 5;
    int j2 = tx * 2, r8 = ty * 8;
    u64 acc[4][2];
#pragma unroll
    for (int p = 0; p < 4; p++) { acc[p][0] = 0ULL; acc[p][1] = 0ULL; }

#pragma unroll 4
    for (int k = 0; k < 128; k++) {
        float2 wv = *(const float2*)(ws + k * 64 + j2);
        u64 w0 = pkdup(wv.x), w1 = pkdup(wv.y);
        ulonglong2 za = *(const ulonglong2*)(as + k * 68 + r8);
        ulonglong2 zb = *(const ulonglong2*)(as + k * 68 + r8 + 4);
        u64 zp[4] = {za.x, za.y, zb.x, zb.y};
#pragma unroll
        for (int p = 0; p < 4; p++) {
            fma2(acc[p][0], zp[p], w0);
            fma2(acc[p][1], zp[p], w1);
        }
    }

    float2 bv = *(const float2*)(b2 + j2);
    float cs0 = 0, cs1 = 0, cq0 = 0, cq1 = 0;
#pragma unroll
    for (int p = 0; p < 4; p++) {
        float a0, a1, b0h, b1h;
        upk2(acc[p][0], a0, b0h);
        upk2(acc[p][1], a1, b1h);
#pragma unroll
        for (int h = 0; h < 2; h++) {
            int gr = row0 + r8 + 2 * p + h;
            float o0 = (h ? b0h : a0) + bv.x;
            float o1 = (h ? b1h : a1) + bv.y;
            if (gr < NNODES) {
                *(float2*)(g_P2 + gr * 64 + j2) = make_float2(o0, o1);
                cs0 += o0; cq0 += o0 * o0;
                cs1 += o1; cq1 += o1 * o1;
            }
        }
    }

    __syncthreads();
    as[ty * 64 + j2] = cs0;       as[ty * 64 + j2 + 1] = cs1;
    as[512 + ty * 64 + j2] = cq0; as[512 + ty * 64 + j2 + 1] = cq1;
    __syncthreads();
    if (t < 128) {
        int col = t & 63;
        int base = (t < 64) ? 0 : 512;
        int off = 256 + wr_p * 128 + ((t < 64) ? 0 : 64);
        float v = 0.0f;
#pragma unroll
        for (int w = 0; w < 8; w++) v += as[base + w * 64 + col];
        atomicAdd(g_stats + off + col, v);
    }
}

// -------- final BN2 (no relu): P2 -> out, reading parity slot rd_p
__global__ void k_bn2(const float* __restrict__ g2v, const float* __restrict__ bb2v,
                      float* __restrict__ out, int rd_p) {
    int i = blockIdx.x * blockDim.x + threadIdx.x;
    if (i >= NNODES * 64) return;
    int j = i & 63;
    const float inv = 1.0f / (float)NNODES;
    int sb = 256 + rd_p * 128;
    float m = g_stats[sb + j] * inv;
    float vq = g_stats[sb + 64 + j] * inv - m * m;
    float rs = rsqrtf(vq + BN_EPS);
    out[i] = (g_P2[i] - m) * rs * __ldg(g2v + j) + __ldg(bb2v + j);
}

extern "C" void kernel_launch(void* const* d_in, const int* in_sizes, int n_in,
                              void* d_out, int out_size) {
    const int*   x   = (const int*)d_in[0];
    const int*   ei  = (const int*)d_in[1];     // [2,E]
    const float* ea  = (const float*)d_in[2];   // [E,7]
    const float* emb = (const float*)d_in[3];   // [1,64]
    const float* We  = (const float*)d_in[4];   // [L,7,64]
    const float* be  = (const float*)d_in[5];   // [L,64]
    const float* eps = (const float*)d_in[6];   // [L]
    const float* W1  = (const float*)d_in[7];   // [L,64,128]
    const float* b1  = (const float*)d_in[8];   // [L,128]
    const float* g1  = (const float*)d_in[9];   // [L,128]
    const float* bb1 = (const float*)d_in[10];  // [L,128]
    const float* W2  = (const float*)d_in[11];  // [L,128,64]
    const float* b2  = (const float*)d_in[12];  // [L,64]
    const float* g2  = (const float*)d_in[13];  // [L,64]
    const float* bb2 = (const float*)d_in[14];  // [L,64]
    float* out = (float*)d_out;

    const int elemBlocks64 = (NNODES * 64 + 255) / 256;   // 12500
    const int gemmBlocks   = (NNODES + 63) / 64;          // 782
    const int edgeBlocks   = (NEDGES + 255) / 256;        // 3125
    const int aggrBlocks   = (NNODES * 32 + 255) / 256;   // 6250

    // CSR build (R6 structure: split g_src + g_ea arrays)
    k_init<<<elemBlocks64, 256>>>(x, emb);
    k_hist<<<edgeBlocks, 256>>>(ei);
    k_scanA<<<SCAN_BLOCKS, 256>>>();
    k_scanB<<<1, 256>>>();
    k_scanC<<<SCAN_BLOCKS, 256>>>();
    k_scatter<<<edgeBlocks, 256>>>(ei);
    k_permute<<<edgeBlocks, 256>>>(ei, ea);

    for (int l = 0; l < LAYERS; l++) {
        int wr_p = l & 1;             // stats parity slot written by gemm2(l)
        int rd_p = (l - 1) & 1;       // slot holding layer l-1's BN2 stats
        const float* pg2  = (l > 0) ? (g2 + (l - 1) * 64) : g2;
        const float* pbb2 = (l > 0) ? (bb2 + (l - 1) * 64) : bb2;
        k_aggr<<<aggrBlocks, 256>>>(We + l * 7 * 64, be + l * 64, eps + l,
                                    pg2, pbb2, (l > 0) ? 1 : 0, rd_p, wr_p);
        k_gemm1<<<gemmBlocks, 256>>>(W1 + l * 64 * 128, b1 + l * 128);
        k_gemm2<<<gemmBlocks, 256>>>(W2 + l * 128 * 64, b2 + l * 64,
                                     g1 + l * 128, bb1 + l * 128, wr_p);
    }
    // Final BN2 (layer 4, no relu): stats in parity slot (LAYERS-1)&1 = 0
    k_bn2<<<elemBlocks64, 256>>>(g2 + (LAYERS - 1) * 64, bb2 + (LAYERS - 1) * 64,
                                 out, (LAYERS - 1) & 1);
}

// round 15
// speedup vs baseline: 1.0905x; 1.0905x over previous
#include <cuda_runtime.h>

#define NNODES 50000
#define NEDGES 800000
#define DIM 64
#define LAYERS 5
#define BN_EPS 1e-5f
#define SCAN_BLOCKS 196   // ceil(50000/256)

// Scratch (__device__ globals; allocation-free rule)
__device__ float g_H[NNODES * DIM];        // node features (layer input)
__device__ float g_Z[NNODES * DIM];        // (1+eps)*h + agg  (GEMM1 input)
__device__ float g_P1[NNODES * 2 * DIM];   // hidden activations [N,128]
__device__ float g_P2[NNODES * DIM];       // mlp output pre-BN2 [N,64]
__device__ float g_stats[512];             // [0:128) sum1 [128:256) sq1 [256:320) sum2 [320:384) sq2
__device__ int   g_deg[NNODES];            // per-dst degree
__device__ int   g_off[NNODES];            // CSR row offsets (exclusive)
__device__ int   g_cur[NNODES];            // scatter cursors
__device__ int   g_csr[NEDGES];            // edge ids grouped by dst
__device__ int   g_bsum[256];              // scan block sums
__device__ int   g_src[NEDGES];            // src node per CSR position
__device__ float g_ea[NEDGES * 7];         // edge attrs permuted to CSR order

typedef unsigned long long u64;

// ---- packed f32x2 helpers ----
__device__ __forceinline__ u64 pkdup(float v) {
    u64 r;
    asm("mov.b64 %0, {%1, %1};" : "=l"(r) : "f"(v));
    return r;
}
__device__ __forceinline__ void upk2(u64 v, float& lo, float& hi) {
    asm("mov.b64 {%0, %1}, %2;" : "=f"(lo), "=f"(hi) : "l"(v));
}
__device__ __forceinline__ void fma2(u64& d, u64 a, u64 b) {
    asm("fma.rn.f32x2 %0, %1, %2, %3;" : "=l"(d) : "l"(a), "l"(b), "l"(d));
}

// ---------------------------------------------------------------- init
__global__ void k_init(const int* __restrict__ x, const float* __restrict__ emb) {
    int i = blockIdx.x * blockDim.x + threadIdx.x;
    if (i < 512) g_stats[i] = 0.0f;
    if (i < NNODES) g_deg[i] = 0;
    if (i < NNODES * DIM) {
        int n = i >> 6, d = i & 63;
        g_H[i] = emb[x[n] * DIM + d];
    }
}

// ---------------------------------------------------- CSR build (per call)
__global__ void k_hist(const int* __restrict__ ei) {
    int e = blockIdx.x * blockDim.x + threadIdx.x;
    if (e < NEDGES) atomicAdd(&g_deg[__ldg(ei + NEDGES + e)], 1);
}

__global__ void k_scanA() {
    __shared__ int ws[8];
    int i = blockIdx.x * 256 + threadIdx.x;
    int lane = threadIdx.x & 31, w = threadIdx.x >> 5;
    int v = (i < NNODES) ? g_deg[i] : 0;
    int x = v;
#pragma unroll
    for (int o = 1; o < 32; o <<= 1) {
        int y = __shfl_up_sync(0xFFFFFFFFu, x, o);
        if (lane >= o) x += y;
    }
    if (lane == 31) ws[w] = x;
    __syncthreads();
    if (w == 0) {
        int y = (lane < 8) ? ws[lane] : 0;
#pragma unroll
        for (int o = 1; o < 8; o <<= 1) {
            int z = __shfl_up_sync(0xFFFFFFFFu, y, o);
            if (lane >= o) y += z;
        }
        if (lane < 8) ws[lane] = y;
    }
    __syncthreads();
    int base = (w > 0) ? ws[w - 1] : 0;
    int incl = x + base;
    if (i < NNODES) g_off[i] = incl - v;
    if (threadIdx.x == 255) g_bsum[blockIdx.x] = incl;
}

__global__ void k_scanB() {
    __shared__ int ws[8];
    int t = threadIdx.x;
    int lane = t & 31, w = t >> 5;
    int v = (t < SCAN_BLOCKS) ? g_bsum[t] : 0;
    int x = v;
#pragma unroll
    for (int o = 1; o < 32; o <<= 1) {
        int y = __shfl_up_sync(0xFFFFFFFFu, x, o);
        if (lane >= o) x += y;
    }
    if (lane == 31) ws[w] = x;
    __syncthreads();
    if (w == 0) {
        int y = (lane < 8) ? ws[lane] : 0;
#pragma unroll
        for (int o = 1; o < 8; o <<= 1) {
            int z = __shfl_up_sync(0xFFFFFFFFu, y, o);
            if (lane >= o) y += z;
        }
        if (lane < 8) ws[lane] = y;
    }
    __syncthreads();
    int base = (w > 0) ? ws[w - 1] : 0;
    if (t < SCAN_BLOCKS) g_bsum[t] = x + base - v;
}

__global__ void k_scanC() {
    int i = blockIdx.x * 256 + threadIdx.x;
    if (i < NNODES) {
        g_off[i] += g_bsum[blockIdx.x];
        g_cur[i] = 0;
    }
}

__global__ void k_scatter(const int* __restrict__ ei) {
    int e = blockIdx.x * blockDim.x + threadIdx.x;
    if (e < NEDGES) {
        int d = __ldg(ei + NEDGES + e);
        int p = atomicAdd(&g_cur[d], 1);
        g_csr[g_off[d] + p] = e;
    }
}

// Permute src ids and edge attrs into CSR order (one-time; makes all 5
// aggregation passes stream sequentially).
__global__ void k_permute(const int* __restrict__ ei, const float* __restrict__ ea) {
    int p = blockIdx.x * blockDim.x + threadIdx.x;
    if (p < NEDGES) {
        int e = g_csr[p];
        g_src[p] = __ldg(ei + e);
        const float* sp = ea + e * 7;
        float* dp = g_ea + p * 7;
#pragma unroll
        for (int k = 0; k < 7; k++) dp[k] = __ldg(sp + k);
    }
}

// -------- aggregation: one warp per node, no atomics, sequential edge stream.
// Z[n] = (1+eps)*H[n] + sum_{p in CSR row n} relu(H[g_src[p]] + g_ea[p]@We + be)
__global__ void k_aggr(const float* __restrict__ We, const float* __restrict__ be,
                       const float* __restrict__ epsp) {
    if (blockIdx.x == 0) {
        g_stats[threadIdx.x] = 0.0f;
        g_stats[256 + threadIdx.x] = 0.0f;
    }
    int node = (blockIdx.x * blockDim.x + threadIdx.x) >> 5;
    if (node >= NNODES) return;
    int lane = threadIdx.x & 31;

    float2 w[7];
#pragma unroll
    for (int k = 0; k < 7; k++) w[k] = *(const float2*)(We + k * DIM + 2 * lane);
    float2 bv = *(const float2*)(be + 2 * lane);

    int beg = g_off[node];
    int end = (node == NNODES - 1) ? NEDGES : g_off[node + 1];

    float a0 = 0.0f, a1 = 0.0f;
#pragma unroll 2
    for (int p = beg; p < end; p++) {
        int s = __ldg(g_src + p);
        const float* ep = g_ea + p * 7;
        float m0 = bv.x, m1 = bv.y;
#pragma unroll
        for (int k = 0; k < 7; k++) {
            float a = __ldg(ep + k);
            m0 = fmaf(a, w[k].x, m0);
            m1 = fmaf(a, w[k].y, m1);
        }
        float2 h2 = *(const float2*)(g_H + s * DIM + 2 * lane);
        a0 += fmaxf(m0 + h2.x, 0.0f);
        a1 += fmaxf(m1 + h2.y, 0.0f);
    }

    float ev = 1.0f + __ldg(epsp);
    float2 hh = *(const float2*)(g_H + node * DIM + 2 * lane);
    *(float2*)(g_Z + node * DIM + 2 * lane) =
        make_float2(fmaf(ev, hh.x, a0), fmaf(ev, hh.y, a1));
}

// ---------------- GEMM1: P1 = Z @ W1 + b1, epilogue: colsum/colsq
__global__ void k_gemm1(const float* __restrict__ W1, const float* __restrict__ b1) {
    __shared__ float zs[64 * 68];    // transposed [k][r]
    __shared__ float ws[64 * 128];
    int t = threadIdx.x;
    int row0 = blockIdx.x * 64;

    for (int i = t; i < 64 * 128; i += 256) ws[i] = W1[i];
    for (int i = t; i < 64 * 64; i += 256) {
        int r = i >> 6, k = i & 63;
        int gr = row0 + r;
        zs[k * 68 + r] = (gr < NNODES) ? g_Z[gr * 64 + k] : 0.0f;
    }
    __syncthreads();

    int tx = t & 31, ty = t >> 5;
    int j4 = tx * 4, r8 = ty * 8;
    u64 acc[4][4];
#pragma unroll
    for (int p = 0; p < 4; p++)
#pragma unroll
        for (int c = 0; c < 4; c++) acc[p][c] = 0ULL;

#pragma unroll 4
    for (int k = 0; k < 64; k++) {
        float4 wv = *(const float4*)(ws + k * 128 + j4);
        u64 wd[4] = {pkdup(wv.x), pkdup(wv.y), pkdup(wv.z), pkdup(wv.w)};
        ulonglong2 za = *(const ulonglong2*)(zs + k * 68 + r8);
        ulonglong2 zb = *(const ulonglong2*)(zs + k * 68 + r8 + 4);
        u64 zp[4] = {za.x, za.y, zb.x, zb.y};
#pragma unroll
        for (int p = 0; p < 4; p++) {
            fma2(acc[p][0], zp[p], wd[0]);
            fma2(acc[p][1], zp[p], wd[1]);
            fma2(acc[p][2], zp[p], wd[2]);
            fma2(acc[p][3], zp[p], wd[3]);
        }
    }

    float4 bv = *(const float4*)(b1 + j4);
    float cs[4] = {0, 0, 0, 0}, cq[4] = {0, 0, 0, 0};
#pragma unroll
    for (int p = 0; p < 4; p++) {
        float o[2][4];
#pragma unroll
        for (int c = 0; c < 4; c++) upk2(acc[p][c], o[0][c], o[1][c]);
#pragma unroll
        for (int h = 0; h < 2; h++) {
            int gr = row0 + r8 + 2 * p + h;
            float o0 = o[h][0] + bv.x, o1 = o[h][1] + bv.y;
            float o2 = o[h][2] + bv.z, o3 = o[h][3] + bv.w;
            if (gr < NNODES) {
                *(float4*)(g_P1 + gr * 128 + j4) = make_float4(o0, o1, o2, o3);
                cs[0] += o0; cq[0] += o0 * o0;
                cs[1] += o1; cq[1] += o1 * o1;
                cs[2] += o2; cq[2] += o2 * o2;
                cs[3] += o3; cq[3] += o3 * o3;
            }
        }
    }

    __syncthreads();
#pragma unroll
    for (int c = 0; c < 4; c++) {
        zs[ty * 128 + j4 + c] = cs[c];
        zs[1024 + ty * 128 + j4 + c] = cq[c];
    }
    __syncthreads();
    {
        int col = t & 127;
        int base = (t < 128) ? 0 : 1024;
        int off = (t < 128) ? 0 : 128;
        float v = 0.0f;
#pragma unroll
        for (int w = 0; w < 8; w++) v += zs[base + w * 128 + col];
        atomicAdd(g_stats + off + col, v);
    }
}

// -------- GEMM2: P2 = relu(BN1(P1)) @ W2 + b2, epilogue colsum/colsq for BN2
__global__ void k_gemm2(const float* __restrict__ W2, const float* __restrict__ b2,
                        const float* __restrict__ g1v, const float* __restrict__ bb1v) {
    __shared__ float as[128 * 68];
    __shared__ float ws[128 * 64];
    __shared__ float sc[128], sh[128];
    int t = threadIdx.x;
    int row0 = blockIdx.x * 64;

    if (t < 128) {
        const float inv = 1.0f / (float)NNODES;
        float m = g_stats[t] * inv;
        float vq = g_stats[128 + t] * inv - m * m;
        float rs = rsqrtf(vq + BN_EPS);
        float s = rs * __ldg(g1v + t);
        sc[t] = s;
        sh[t] = __ldg(bb1v + t) - m * s;
    }
    for (int i = t; i < 128 * 64; i += 256) ws[i] = W2[i];
    __syncthreads();

    for (int i = t; i < 64 * 128; i += 256) {
        int r = i >> 7, k = i & 127;
        int gr = row0 + r;
        float v = 0.0f;
        if (gr < NNODES) v = fmaxf(g_P1[gr * 128 + k] * sc[k] + sh[k], 0.0f);
        as[k * 68 + r] = v;
    }
    __syncthreads();

    int tx = t & 31, ty = t >> 5;
    int j2 = tx * 2, r8 = ty * 8;
    u64 acc[4][2];
#pragma unroll
    for (int p = 0; p < 4; p++) { acc[p][0] = 0ULL; acc[p][1] = 0ULL; }

#pragma unroll 4
    for (int k = 0; k < 128; k++) {
        float2 wv = *(const float2*)(ws + k * 64 + j2);
        u64 w0 = pkdup(wv.x), w1 = pkdup(wv.y);
        ulonglong2 za = *(const ulonglong2*)(as + k * 68 + r8);
        ulonglong2 zb = *(const ulonglong2*)(as + k * 68 + r8 + 4);
        u64 zp[4] = {za.x, za.y, zb.x, zb.y};
#pragma unroll
        for (int p = 0; p < 4; p++) {
            fma2(acc[p][0], zp[p], w0);
            fma2(acc[p][1], zp[p], w1);
        }
    }

    float2 bv = *(const float2*)(b2 + j2);
    float cs0 = 0, cs1 = 0, cq0 = 0, cq1 = 0;
#pragma unroll
    for (int p = 0; p < 4; p++) {
        float a0, a1, b0h, b1h;
        upk2(acc[p][0], a0, b0h);
        upk2(acc[p][1], a1, b1h);
#pragma unroll
        for (int h = 0; h < 2; h++) {
            int gr = row0 + r8 + 2 * p + h;
            float o0 = (h ? b0h : a0) + bv.x;
            float o1 = (h ? b1h : a1) + bv.y;
            if (gr < NNODES) {
                *(float2*)(g_P2 + gr * 64 + j2) = make_float2(o0, o1);
                cs0 += o0; cq0 += o0 * o0;
                cs1 += o1; cq1 += o1 * o1;
            }
        }
    }

    __syncthreads();
    as[ty * 64 + j2] = cs0;       as[ty * 64 + j2 + 1] = cs1;
    as[512 + ty * 64 + j2] = cq0; as[512 + ty * 64 + j2 + 1] = cq1;
    __syncthreads();
    if (t < 128) {
        int col = t & 63;
        int base = (t < 64) ? 0 : 512;
        int off = (t < 64) ? 256 : 320;
        float v = 0.0f;
#pragma unroll
        for (int w = 0; w < 8; w++) v += as[base + w * 64 + col];
        atomicAdd(g_stats + off + col, v);
    }
}

// -------- BN2 (+optional ReLU): P2 -> H (intermediate, relu) or out (last)
__global__ void k_bn2(const float* __restrict__ g2v, const float* __restrict__ bb2v,
                      float* __restrict__ out, int relu) {
    int i = blockIdx.x * blockDim.x + threadIdx.x;
    if (i >= NNODES * 64) return;
    int j = i & 63;
    const float inv = 1.0f / (float)NNODES;
    float m = g_stats[256 + j] * inv;
    float vq = g_stats[320 + j] * inv - m * m;
    float rs = rsqrtf(vq + BN_EPS);
    float val = (g_P2[i] - m) * rs * __ldg(g2v + j) + __ldg(bb2v + j);
    if (relu) val = fmaxf(val, 0.0f);
    float* dst = out ? out : g_H;
    dst[i] = val;
}

extern "C" void kernel_launch(void* const* d_in, const int* in_sizes, int n_in,
                              void* d_out, int out_size) {
    const int*   x   = (const int*)d_in[0];
    const int*   ei  = (const int*)d_in[1];     // [2,E]
    const float* ea  = (const float*)d_in[2];   // [E,7]
    const float* emb = (const float*)d_in[3];   // [1,64]
    const float* We  = (const float*)d_in[4];   // [L,7,64]
    const float* be  = (const float*)d_in[5];   // [L,64]
    const float* eps = (const float*)d_in[6];   // [L]
    const float* W1  = (const float*)d_in[7];   // [L,64,128]
    const float* b1  = (const float*)d_in[8];   // [L,128]
    const float* g1  = (const float*)d_in[9];   // [L,128]
    const float* bb1 = (const float*)d_in[10];  // [L,128]
    const float* W2  = (const float*)d_in[11];  // [L,128,64]
    const float* b2  = (const float*)d_in[12];  // [L,64]
    const float* g2  = (const float*)d_in[13];  // [L,64]
    const float* bb2 = (const float*)d_in[14];  // [L,64]
    float* out = (float*)d_out;

    const int elemBlocks64 = (NNODES * 64 + 255) / 256;   // 12500
    const int gemmBlocks   = (NNODES + 63) / 64;          // 782
    const int edgeBlocks   = (NEDGES + 255) / 256;        // 3125
    const int aggrBlocks   = (NNODES * 32 + 255) / 256;   // 6250

    // CSR build (dst-grouped edge lists; edge_index constant across layers)
    k_init<<<elemBlocks64, 256>>>(x, emb);
    k_hist<<<edgeBlocks, 256>>>(ei);
    k_scanA<<<SCAN_BLOCKS, 256>>>();
    k_scanB<<<1, 256>>>();
    k_scanC<<<SCAN_BLOCKS, 256>>>();
    k_scatter<<<edgeBlocks, 256>>>(ei);
    k_permute<<<edgeBlocks, 256>>>(ei, ea);

    for (int l = 0; l < LAYERS; l++) {
        k_aggr<<<aggrBlocks, 256>>>(We + l * 7 * 64, be + l * 64, eps + l);
        k_gemm1<<<gemmBlocks, 256>>>(W1 + l * 64 * 128, b1 + l * 128);
        k_gemm2<<<gemmBlocks, 256>>>(W2 + l * 128 * 64, b2 + l * 64,
                                     g1 + l * 128, bb1 + l * 128);
        if (l == LAYERS - 1) {
            k_bn2<<<elemBlocks64, 256>>>(g2 + l * 64, bb2 + l * 64, out, 0);
        } else {
            k_bn2<<<elemBlocks64, 256>>>(g2 + l * 64, bb2 + l * 64, nullptr, 1);
        }
    }
}

// round 16
// speedup vs baseline: 1.1131x; 1.0207x over previous
#include <cuda_runtime.h>

#define NNODES 50000
#define NEDGES 800000
#define DIM 64
#define LAYERS 5
#define BN_EPS 1e-5f
#define SCAN_BLOCKS 196   // ceil(50000/256)

// Scratch (__device__ globals; allocation-free rule)
__device__ float g_H[NNODES * DIM];        // node features (layer input)
__device__ float g_Z[NNODES * DIM];        // (1+eps)*h + agg  (GEMM1 input)
__device__ float g_P1[NNODES * 2 * DIM];   // hidden activations [N,128]
__device__ float g_P2[NNODES * DIM];       // mlp output pre-BN2 [N,64]
__device__ float g_stats[512];             // [0:128) sum1 [128:256) sq1 [256:320) sum2 [320:384) sq2
__device__ int   g_deg[NNODES];            // per-dst degree
__device__ int   g_off[NNODES];            // CSR row offsets (exclusive)
__device__ int   g_cur[NNODES];            // scatter cursors
__device__ int   g_csr[NEDGES];            // edge ids grouped by dst
__device__ int   g_bsum[256];              // scan block sums

typedef unsigned long long u64;

// ---- packed f32x2 helpers ----
__device__ __forceinline__ u64 pkdup(float v) {
    u64 r;
    asm("mov.b64 %0, {%1, %1};" : "=l"(r) : "f"(v));
    return r;
}
__device__ __forceinline__ void upk2(u64 v, float& lo, float& hi) {
    asm("mov.b64 {%0, %1}, %2;" : "=f"(lo), "=f"(hi) : "l"(v));
}
__device__ __forceinline__ void fma2(u64& d, u64 a, u64 b) {
    asm("fma.rn.f32x2 %0, %1, %2, %3;" : "=l"(d) : "l"(a), "l"(b), "l"(d));
}

// ---------------------------------------------------------------- init
__global__ void k_init(const int* __restrict__ x, const float* __restrict__ emb) {
    int i = blockIdx.x * blockDim.x + threadIdx.x;
    if (i < 512) g_stats[i] = 0.0f;
    if (i < NNODES) g_deg[i] = 0;
    if (i < NNODES * DIM) {
        int n = i >> 6, d = i & 63;
        g_H[i] = emb[x[n] * DIM + d];
    }
}

// ---------------------------------------------------- CSR build (per call)
__global__ void k_hist(const int* __restrict__ ei) {
    int e = blockIdx.x * blockDim.x + threadIdx.x;
    if (e < NEDGES) atomicAdd(&g_deg[__ldg(ei + NEDGES + e)], 1);
}

__global__ void k_scanA() {
    __shared__ int ws[8];
    int i = blockIdx.x * 256 + threadIdx.x;
    int lane = threadIdx.x & 31, w = threadIdx.x >> 5;
    int v = (i < NNODES) ? g_deg[i] : 0;
    int x = v;
#pragma unroll
    for (int o = 1; o < 32; o <<= 1) {
        int y = __shfl_up_sync(0xFFFFFFFFu, x, o);
        if (lane >= o) x += y;
    }
    if (lane == 31) ws[w] = x;
    __syncthreads();
    if (w == 0) {
        int y = (lane < 8) ? ws[lane] : 0;
#pragma unroll
        for (int o = 1; o < 8; o <<= 1) {
            int z = __shfl_up_sync(0xFFFFFFFFu, y, o);
            if (lane >= o) y += z;
        }
        if (lane < 8) ws[lane] = y;
    }
    __syncthreads();
    int base = (w > 0) ? ws[w - 1] : 0;
    int incl = x + base;
    if (i < NNODES) g_off[i] = incl - v;
    if (threadIdx.x == 255) g_bsum[blockIdx.x] = incl;
}

__global__ void k_scanB() {
    __shared__ int ws[8];
    int t = threadIdx.x;
    int lane = t & 31, w = t >> 5;
    int v = (t < SCAN_BLOCKS) ? g_bsum[t] : 0;
    int x = v;
#pragma unroll
    for (int o = 1; o < 32; o <<= 1) {
        int y = __shfl_up_sync(0xFFFFFFFFu, x, o);
        if (lane >= o) x += y;
    }
    if (lane == 31) ws[w] = x;
    __syncthreads();
    if (w == 0) {
        int y = (lane < 8) ? ws[lane] : 0;
#pragma unroll
        for (int o = 1; o < 8; o <<= 1) {
            int z = __shfl_up_sync(0xFFFFFFFFu, y, o);
            if (lane >= o) y += z;
        }
        if (lane < 8) ws[lane] = y;
    }
    __syncthreads();
    int base = (w > 0) ? ws[w - 1] : 0;
    if (t < SCAN_BLOCKS) g_bsum[t] = x + base - v;
}

__global__ void k_scanC() {
    int i = blockIdx.x * 256 + threadIdx.x;
    if (i < NNODES) {
        g_off[i] += g_bsum[blockIdx.x];
        g_cur[i] = 0;
    }
}

__global__ void k_scatter(const int* __restrict__ ei) {
    int e = blockIdx.x * blockDim.x + threadIdx.x;
    if (e < NEDGES) {
        int d = __ldg(ei + NEDGES + e);
        int p = atomicAdd(&g_cur[d], 1);
        g_csr[g_off[d] + p] = e;
    }
}

// -------- aggregation: one warp per node, no atomics.
// Z[n] = (1+eps)*H[n] + sum_{e: dst=n} relu(H[src(e)] + ea[e]@We + be)
// Lane owns 2 features. Block 0 zeroes stats for this layer.
__global__ void k_aggr(const int* __restrict__ ei, const float* __restrict__ ea,
                       const float* __restrict__ We, const float* __restrict__ be,
                       const float* __restrict__ epsp) {
    if (blockIdx.x == 0) {
        g_stats[threadIdx.x] = 0.0f;
        g_stats[256 + threadIdx.x] = 0.0f;
    }
    int node = (blockIdx.x * blockDim.x + threadIdx.x) >> 5;
    if (node >= NNODES) return;
    int lane = threadIdx.x & 31;

    float2 w[7];
#pragma unroll
    for (int k = 0; k < 7; k++) w[k] = *(const float2*)(We + k * DIM + 2 * lane);
    float2 bv = *(const float2*)(be + 2 * lane);

    int beg = g_off[node];
    int end = (node == NNODES - 1) ? NEDGES : g_off[node + 1];

    float a0 = 0.0f, a1 = 0.0f;
#pragma unroll 2
    for (int p = beg; p < end; p++) {
        int e = __ldg(g_csr + p);
        int s = __ldg(ei + e);
        const float* ep = ea + e * 7;
        float m0 = bv.x, m1 = bv.y;
#pragma unroll
        for (int k = 0; k < 7; k++) {
            float a = __ldg(ep + k);
            m0 = fmaf(a, w[k].x, m0);
            m1 = fmaf(a, w[k].y, m1);
        }
        float2 h2 = *(const float2*)(g_H + s * DIM + 2 * lane);
        a0 += fmaxf(m0 + h2.x, 0.0f);
        a1 += fmaxf(m1 + h2.y, 0.0f);
    }

    float ev = 1.0f + __ldg(epsp);
    float2 hh = *(const float2*)(g_H + node * DIM + 2 * lane);
    *(float2*)(g_Z + node * DIM + 2 * lane) =
        make_float2(fmaf(ev, hh.x, a0), fmaf(ev, hh.y, a1));
}

// ---------------- GEMM1: P1 = Z @ W1 + b1, epilogue: colsum/colsq
__global__ void k_gemm1(const float* __restrict__ W1, const float* __restrict__ b1) {
    __shared__ float zs[64 * 68];    // transposed [k][r]
    __shared__ float ws[64 * 128];
    int t = threadIdx.x;
    int row0 = blockIdx.x * 64;

    for (int i = t; i < 64 * 128; i += 256) ws[i] = W1[i];
    for (int i = t; i < 64 * 64; i += 256) {
        int r = i >> 6, k = i & 63;
        int gr = row0 + r;
        zs[k * 68 + r] = (gr < NNODES) ? g_Z[gr * 64 + k] : 0.0f;
    }
    __syncthreads();

    int tx = t & 31, ty = t >> 5;
    int j4 = tx * 4, r8 = ty * 8;
    u64 acc[4][4];
#pragma unroll
    for (int p = 0; p < 4; p++)
#pragma unroll
        for (int c = 0; c < 4; c++) acc[p][c] = 0ULL;

#pragma unroll 4
    for (int k = 0; k < 64; k++) {
        float4 wv = *(const float4*)(ws + k * 128 + j4);
        u64 wd[4] = {pkdup(wv.x), pkdup(wv.y), pkdup(wv.z), pkdup(wv.w)};
        ulonglong2 za = *(const ulonglong2*)(zs + k * 68 + r8);
        ulonglong2 zb = *(const ulonglong2*)(zs + k * 68 + r8 + 4);
        u64 zp[4] = {za.x, za.y, zb.x, zb.y};
#pragma unroll
        for (int p = 0; p < 4; p++) {
            fma2(acc[p][0], zp[p], wd[0]);
            fma2(acc[p][1], zp[p], wd[1]);
            fma2(acc[p][2], zp[p], wd[2]);
            fma2(acc[p][3], zp[p], wd[3]);
        }
    }

    float4 bv = *(const float4*)(b1 + j4);
    float cs[4] = {0, 0, 0, 0}, cq[4] = {0, 0, 0, 0};
#pragma unroll
    for (int p = 0; p < 4; p++) {
        float o[2][4];
#pragma unroll
        for (int c = 0; c < 4; c++) upk2(acc[p][c], o[0][c], o[1][c]);
#pragma unroll
        for (int h = 0; h < 2; h++) {
            int gr = row0 + r8 + 2 * p + h;
            float o0 = o[h][0] + bv.x, o1 = o[h][1] + bv.y;
            float o2 = o[h][2] + bv.z, o3 = o[h][3] + bv.w;
            if (gr < NNODES) {
                *(float4*)(g_P1 + gr * 128 + j4) = make_float4(o0, o1, o2, o3);
                cs[0] += o0; cq[0] += o0 * o0;
                cs[1] += o1; cq[1] += o1 * o1;
                cs[2] += o2; cq[2] += o2 * o2;
                cs[3] += o3; cq[3] += o3 * o3;
            }
        }
    }

    __syncthreads();  // reuse zs as reduction scratch
#pragma unroll
    for (int c = 0; c < 4; c++) {
        zs[ty * 128 + j4 + c] = cs[c];
        zs[1024 + ty * 128 + j4 + c] = cq[c];
    }
    __syncthreads();
    {
        int col = t & 127;
        int base = (t < 128) ? 0 : 1024;
        int off = (t < 128) ? 0 : 128;
        float v = 0.0f;
#pragma unroll
        for (int w = 0; w < 8; w++) v += zs[base + w * 128 + col];
        atomicAdd(g_stats + off + col, v);
    }
}

// -------- GEMM2: P2 = relu(BN1(P1)) @ W2 + b2, epilogue colsum/colsq for BN2
__global__ void k_gemm2(const float* __restrict__ W2, const float* __restrict__ b2,
                        const float* __restrict__ g1v, const float* __restrict__ bb1v) {
    __shared__ float as[128 * 68];
    __shared__ float ws[128 * 64];
    __shared__ float sc[128], sh[128];
    int t = threadIdx.x;
    int row0 = blockIdx.x * 64;

    if (t < 128) {
        const float inv = 1.0f / (float)NNODES;
        float m = g_stats[t] * inv;
        float vq = g_stats[128 + t] * inv - m * m;
        float rs = rsqrtf(vq + BN_EPS);
        float s = rs * __ldg(g1v + t);
        sc[t] = s;
        sh[t] = __ldg(bb1v + t) - m * s;
    }
    for (int i = t; i < 128 * 64; i += 256) ws[i] = W2[i];
    __syncthreads();

    for (int i = t; i < 64 * 128; i += 256) {
        int r = i >> 7, k = i & 127;
        int gr = row0 + r;
        float v = 0.0f;
        if (gr < NNODES) v = fmaxf(g_P1[gr * 128 + k] * sc[k] + sh[k], 0.0f);
        as[k * 68 + r] = v;
    }
    __syncthreads();

    int tx = t & 31, ty = t >> 5;
    int j2 = tx * 2, r8 = ty * 8;
    u64 acc[4][2];
#pragma unroll
    for (int p = 0; p < 4; p++) { acc[p][0] = 0ULL; acc[p][1] = 0ULL; }

#pragma unroll 4
    for (int k = 0; k < 128; k++) {
        float2 wv = *(const float2*)(ws + k * 64 + j2);
        u64 w0 = pkdup(wv.x), w1 = pkdup(wv.y);
        ulonglong2 za = *(const ulonglong2*)(as + k * 68 + r8);
        ulonglong2 zb = *(const ulonglong2*)(as + k * 68 + r8 + 4);
        u64 zp[4] = {za.x, za.y, zb.x, zb.y};
#pragma unroll
        for (int p = 0; p < 4; p++) {
            fma2(acc[p][0], zp[p], w0);
            fma2(acc[p][1], zp[p], w1);
        }
    }

    float2 bv = *(const float2*)(b2 + j2);
    float cs0 = 0, cs1 = 0, cq0 = 0, cq1 = 0;
#pragma unroll
    for (int p = 0; p < 4; p++) {
        float a0, a1, b0h, b1h;
        upk2(acc[p][0], a0, b0h);
        upk2(acc[p][1], a1, b1h);
#pragma unroll
        for (int h = 0; h < 2; h++) {
            int gr = row0 + r8 + 2 * p + h;
            float o0 = (h ? b0h : a0) + bv.x;
            float o1 = (h ? b1h : a1) + bv.y;
            if (gr < NNODES) {
                *(float2*)(g_P2 + gr * 64 + j2) = make_float2(o0, o1);
                cs0 += o0; cq0 += o0 * o0;
                cs1 += o1; cq1 += o1 * o1;
            }
        }
    }

    __syncthreads();  // reuse as[] for reduction
    as[ty * 64 + j2] = cs0;       as[ty * 64 + j2 + 1] = cs1;
    as[512 + ty * 64 + j2] = cq0; as[512 + ty * 64 + j2 + 1] = cq1;
    __syncthreads();
    if (t < 128) {
        int col = t & 63;
        int base = (t < 64) ? 0 : 512;
        int off = (t < 64) ? 256 : 320;
        float v = 0.0f;
#pragma unroll
        for (int w = 0; w < 8; w++) v += as[base + w * 64 + col];
        atomicAdd(g_stats + off + col, v);
    }
}

// -------- BN2 (+optional ReLU): P2 -> H (intermediate, relu) or out (last)
__global__ void k_bn2(const float* __restrict__ g2v, const float* __restrict__ bb2v,
                      float* __restrict__ out, int relu) {
    int i = blockIdx.x * blockDim.x + threadIdx.x;
    if (i >= NNODES * 64) return;
    int j = i & 63;
    const float inv = 1.0f / (float)NNODES;
    float m = g_stats[256 + j] * inv;
    float vq = g_stats[320 + j] * inv - m * m;
    float rs = rsqrtf(vq + BN_EPS);
    float val = (g_P2[i] - m) * rs * __ldg(g2v + j) + __ldg(bb2v + j);
    if (relu) val = fmaxf(val, 0.0f);
    float* dst = out ? out : g_H;
    dst[i] = val;
}

extern "C" void kernel_launch(void* const* d_in, const int* in_sizes, int n_in,
                              void* d_out, int out_size) {
    const int*   x   = (const int*)d_in[0];
    const int*   ei  = (const int*)d_in[1];     // [2,E]
    const float* ea  = (const float*)d_in[2];   // [E,7]
    const float* emb = (const float*)d_in[3];   // [1,64]
    const float* We  = (const float*)d_in[4];   // [L,7,64]
    const float* be  = (const float*)d_in[5];   // [L,64]
    const float* eps = (const float*)d_in[6];   // [L]
    const float* W1  = (const float*)d_in[7];   // [L,64,128]
    const float* b1  = (const float*)d_in[8];   // [L,128]
    const float* g1  = (const float*)d_in[9];   // [L,128]
    const float* bb1 = (const float*)d_in[10];  // [L,128]
    const float* W2  = (const float*)d_in[11];  // [L,128,64]
    const float* b2  = (const float*)d_in[12];  // [L,64]
    const float* g2  = (const float*)d_in[13];  // [L,64]
    const float* bb2 = (const float*)d_in[14];  // [L,64]
    float* out = (float*)d_out;

    const int elemBlocks64 = (NNODES * 64 + 255) / 256;   // 12500
    const int gemmBlocks   = (NNODES + 63) / 64;          // 782
    const int edgeBlocks   = (NEDGES + 255) / 256;        // 3125
    const int aggrBlocks   = (NNODES * 32 + 255) / 256;   // 6250

    // CSR build (dst-grouped edge lists; edge_index constant across layers)
    k_init<<<elemBlocks64, 256>>>(x, emb);
    k_hist<<<edgeBlocks, 256>>>(ei);
    k_scanA<<<SCAN_BLOCKS, 256>>>();
    k_scanB<<<1, 256>>>();
    k_scanC<<<SCAN_BLOCKS, 256>>>();
    k_scatter<<<edgeBlocks, 256>>>(ei);

    for (int l = 0; l < LAYERS; l++) {
        k_aggr<<<aggrBlocks, 256>>>(ei, ea, We + l * 7 * 64, be + l * 64, eps + l);
        k_gemm1<<<gemmBlocks, 256>>>(W1 + l * 64 * 128, b1 + l * 128);
        k_gemm2<<<gemmBlocks, 256>>>(W2 + l * 128 * 64, b2 + l * 64,
                                     g1 + l * 128, bb1 + l * 128);
        if (l == LAYERS - 1) {
            k_bn2<<<elemBlocks64, 256>>>(g2 + l * 64, bb2 + l * 64, out, 0);
        } else {
            k_bn2<<<elemBlocks64, 256>>>(g2 + l * 64, bb2 + l * 64, nullptr, 1);
        }
    }
}